// round 9
// baseline (speedup 1.0000x reference)
#include <cuda_runtime.h>
#include <stdint.h>
#include <math.h>

// Problem constants (fixed by reference setup_inputs)
#define BB 8192
#define DD 1024
#define TEMP 10.0f
#define QS 512.0f               // int8 quantization scale (sim = acc / QS^2)

// GEMM tiling: CTA 128x128, 4 warps (2x2), warp tile 64x64, BK=64 int8, 3 stages
#define BM 128
#define BN 128
#define BK 64
#define STAGES 3
#define ROWB 80                 // bytes per smem row (64 s8 + 16B pad) -> conflict-free
#define STAGE_BYTES (2 * BM * ROWB)   // A(10240) + B(10240) = 20480
#define NTX 64
#define NTY 64

// Scratch (allocation-free rule: __device__ globals)
__device__ int8_t g_img8[BB * DD];   // normalized image * 512, s8
__device__ int8_t g_txt8[BB * DD];   // normalized text  * 512, s8
__device__ float g_partial[NTX * NTY];

// ---------------------------------------------------------------------------
// helpers
// ---------------------------------------------------------------------------
__device__ __forceinline__ uint32_t smem_u32(const void* p) {
    uint32_t a;
    asm("{ .reg .u64 t; cvta.to.shared.u64 t, %1; cvt.u32.u64 %0, t; }" : "=r"(a) : "l"(p));
    return a;
}
__device__ __forceinline__ void cp_async16(uint32_t dst, const void* src) {
    asm volatile("cp.async.cg.shared.global [%0], [%1], 16;" :: "r"(dst), "l"(src));
}
__device__ __forceinline__ void cp_commit() {
    asm volatile("cp.async.commit_group;" ::: "memory");
}
__device__ __forceinline__ void cp_wait1() {
    asm volatile("cp.async.wait_group 1;" ::: "memory");
}
__device__ __forceinline__ void ldsm_x4(uint32_t* r, uint32_t addr) {
    asm volatile("ldmatrix.sync.aligned.m8n8.x4.shared.b16 {%0,%1,%2,%3}, [%4];"
                 : "=r"(r[0]), "=r"(r[1]), "=r"(r[2]), "=r"(r[3]) : "r"(addr));
}
// s8 x s8 -> s32 accumulate, K=32
__device__ __forceinline__ void mma_s8(int* c, const uint32_t* a, const uint32_t* b) {
    asm volatile(
        "mma.sync.aligned.m16n8k32.row.col.s32.s8.s8.s32 "
        "{%0,%1,%2,%3}, {%4,%5,%6,%7}, {%8,%9}, {%0,%1,%2,%3};"
        : "+r"(c[0]), "+r"(c[1]), "+r"(c[2]), "+r"(c[3])
        : "r"(a[0]), "r"(a[1]), "r"(a[2]), "r"(a[3]), "r"(b[0]), "r"(b[1]));
}

// ---------------------------------------------------------------------------
// Kernel 1: L2-normalize rows, emit s8 scaled by 512.
// blocks [0,BB)->image, [BB,2BB)->text. 256 thr, 4 floats -> 4 bytes each.
// ---------------------------------------------------------------------------
__global__ __launch_bounds__(256) void normalize_s8_k(const float* __restrict__ text,
                                                      const float* __restrict__ image) {
    int row = blockIdx.x;
    const float* src;
    int8_t* dst;
    if (row < BB) {
        src = image + (size_t)row * DD;
        dst = g_img8 + (size_t)row * DD;
    } else {
        int r = row - BB;
        src = text + (size_t)r * DD;
        dst = g_txt8 + (size_t)r * DD;
    }
    int t = threadIdx.x;
    float4 v = ((const float4*)src)[t];
    float ss = v.x * v.x + v.y * v.y + v.z * v.z + v.w * v.w;
    #pragma unroll
    for (int o = 16; o > 0; o >>= 1) ss += __shfl_xor_sync(0xffffffffu, ss, o);

    __shared__ float ws[8];
    int warp = t >> 5, lane = t & 31;
    if (lane == 0) ws[warp] = ss;
    __syncthreads();
    if (warp == 0) {
        float s2 = (lane < 8) ? ws[lane] : 0.f;
        #pragma unroll
        for (int o = 4; o > 0; o >>= 1) s2 += __shfl_xor_sync(0xffffffffu, s2, o);
        if (lane == 0) ws[0] = s2;
    }
    __syncthreads();
    float s = QS / fmaxf(sqrtf(ws[0]), 1e-12f);   // torch F.normalize eps
    // quantize (values bounded ~|89|, clamp anyway for safety)
    int xi = __float2int_rn(fminf(fmaxf(v.x * s, -127.f), 127.f));
    int yi = __float2int_rn(fminf(fmaxf(v.y * s, -127.f), 127.f));
    int zi = __float2int_rn(fminf(fmaxf(v.z * s, -127.f), 127.f));
    int wi = __float2int_rn(fminf(fmaxf(v.w * s, -127.f), 127.f));
    uint32_t packed = (uint32_t)(xi & 0xFF) | ((uint32_t)(yi & 0xFF) << 8) |
                      ((uint32_t)(zi & 0xFF) << 16) | ((uint32_t)(wi & 0xFF) << 24);
    *reinterpret_cast<uint32_t*>(dst + t * 4) = packed;
}

// ---------------------------------------------------------------------------
// Kernel 2: s8 IMMA GEMM (128x128 CTA, 4 warps, warp tile 64x64, s32 acc)
// + fused sigmoid loss epilogue. Single barrier per K-iter.
// ---------------------------------------------------------------------------
__global__ __launch_bounds__(128, 2) void gemm_loss_s8(const float* __restrict__ bias) {
    extern __shared__ char smem[];
    const uint32_t sbase = smem_u32(smem);
    const int tid = threadIdx.x;
    const int wid = tid >> 5;
    const int lane = tid & 31;
    const int bx = blockIdx.x;   // N tile (txt rows)
    const int by = blockIdx.y;   // M tile (img rows)

    const int wm = wid >> 1;     // 0..1 (64-row slab)
    const int wn = wid & 1;      // 0..1 (64-col slab)

    // accumulators: 4 m16 x 8 n8 x 4 s32
    int acc[4][8][4];
    #pragma unroll
    for (int i = 0; i < 4; i++)
        #pragma unroll
        for (int j = 0; j < 8; j++)
            #pragma unroll
            for (int k = 0; k < 4; k++) acc[i][j][k] = 0;

    const int8_t* ag = g_img8 + (size_t)(by * BM) * DD;
    const int8_t* bg = g_txt8 + (size_t)(bx * BN) * DD;

    // loader: stage = A(128x64B) + B(128x64B) = 1024 x 16B chunks, 8 per thread
    auto issue_stage = [&](int kc, int stg) {
        uint32_t abase = sbase + stg * STAGE_BYTES;
        #pragma unroll
        for (int o = 0; o < 8; o++) {
            int idx = o * 128 + tid;
            int r = (idx >> 2) & 127;
            int ch = idx & 3;
            if (idx < 512) {
                cp_async16(abase + r * ROWB + ch * 16,
                           ag + (size_t)r * DD + kc * BK + ch * 16);
            } else {
                cp_async16(abase + 10240 + r * ROWB + ch * 16,
                           bg + (size_t)r * DD + kc * BK + ch * 16);
            }
        }
        cp_commit();
    };

    issue_stage(0, 0);
    issue_stage(1, 1);

    // ldmatrix address components (b16 view; byte-operand mapping validated R7)
    const int arow = lane & 15;
    const uint32_t ahi = (lane >> 4) * 16;   // upper k16 bytes = +16 B
    const int bmi = lane >> 3;
    const int brow = lane & 7;
    const int bnoff = (bmi >> 1) * 8;
    const uint32_t bhi = (bmi & 1) * 16;

    const int NKI = DD / BK;   // 16
    for (int kc = 0; kc < NKI; kc++) {
        cp_wait1();
        __syncthreads();   // single barrier: orders prior-iter smem reads before
                           // overwrite of stage (kc+2)%3 AND publishes stage kc%3
        if (kc + 2 < NKI) issue_stage(kc + 2, (kc + 2) % STAGES);
        else cp_commit();   // keep wait_group accounting uniform

        const uint32_t abase = sbase + (kc % STAGES) * STAGE_BYTES;
        const uint32_t bbase = abase + 10240;

        #pragma unroll
        for (int ks = 0; ks < 2; ks++) {     // two k32 steps per 64B chunk
            uint32_t afrag[4][4], bfrag[4][4];
            #pragma unroll
            for (int mt = 0; mt < 4; mt++)
                ldsm_x4(afrag[mt], abase + (wm * 64 + mt * 16 + arow) * ROWB + ks * 32 + ahi);
            #pragma unroll
            for (int p = 0; p < 4; p++)      // n8 pairs (2p, 2p+1)
                ldsm_x4(bfrag[p], bbase + (wn * 64 + p * 16 + bnoff + brow) * ROWB + ks * 32 + bhi);

            #pragma unroll
            for (int mt = 0; mt < 4; mt++)
                #pragma unroll
                for (int nt = 0; nt < 8; nt++)
                    mma_s8(acc[mt][nt], afrag[mt], &bfrag[nt >> 1][(nt & 1) * 2]);
        }
        // no trailing barrier (single-barrier scheme)
    }

    // ---- fused loss epilogue ----
    // s32 acc layout: c0:(gr,gc) c1:(gr,gc+1) c2:(gr+8,gc) c3:(gr+8,gc+1)
    // sim = acc / QS^2;  logit = bias - TEMP*sim
    const float b0v = bias[0];
    const float lscale = -TEMP / (QS * QS);
    const int gr = lane >> 2;
    const int gc = (lane & 3) * 2;
    float local = 0.f;
    #pragma unroll
    for (int mt = 0; mt < 4; mt++) {
        const int m0 = by * BM + wm * 64 + mt * 16 + gr;
        #pragma unroll
        for (int nt = 0; nt < 8; nt++) {
            const int n0 = bx * BN + wn * 64 + nt * 8 + gc;
            #pragma unroll
            for (int k = 0; k < 4; k++) {
                int m = m0 + (k >> 1) * 8;
                int n = n0 + (k & 1);
                float logit = fmaf((float)acc[mt][nt][k], lscale, b0v);
                float y = (m == n) ? logit : -logit;
                local += fmaxf(y, 0.f) + __logf(1.f + __expf(-fabsf(y)));
            }
        }
    }

    // block reduce -> one partial per CTA (deterministic, no atomics)
    #pragma unroll
    for (int o = 16; o > 0; o >>= 1) local += __shfl_xor_sync(0xffffffffu, local, o);
    __shared__ float red[4];
    if (lane == 0) red[wid] = local;
    __syncthreads();
    if (tid == 0) {
        g_partial[by * NTX + bx] = red[0] + red[1] + red[2] + red[3];
    }
}

// ---------------------------------------------------------------------------
// Kernel 3: reduce NTX*NTY partials -> scalar
// ---------------------------------------------------------------------------
__global__ __launch_bounds__(256) void final_reduce_k(float* __restrict__ out) {
    int t = threadIdx.x;
    float s = 0.f;
    for (int i = t; i < NTX * NTY; i += 256) s += g_partial[i];
    #pragma unroll
    for (int o = 16; o > 0; o >>= 1) s += __shfl_xor_sync(0xffffffffu, s, o);
    __shared__ float ws[8];
    if ((t & 31) == 0) ws[t >> 5] = s;
    __syncthreads();
    if (t == 0) {
        float tot = 0.f;
        #pragma unroll
        for (int i = 0; i < 8; i++) tot += ws[i];
        out[0] = tot / (float)BB;
    }
}

// ---------------------------------------------------------------------------
extern "C" void kernel_launch(void* const* d_in, const int* in_sizes, int n_in,
                              void* d_out, int out_size) {
    const float* text  = (const float*)d_in[0];
    const float* image = (const float*)d_in[1];
    const float* bias  = (const float*)d_in[2];

    const int smem_bytes = STAGES * STAGE_BYTES;   // 61440
    cudaFuncSetAttribute(gemm_loss_s8, cudaFuncAttributeMaxDynamicSharedMemorySize, smem_bytes);

    normalize_s8_k<<<2 * BB, 256>>>(text, image);
    gemm_loss_s8<<<dim3(NTX, NTY), 128, smem_bytes>>>(bias);
    final_reduce_k<<<1, 256>>>((float*)d_out);
}

// round 10
// speedup vs baseline: 2.4295x; 2.4295x over previous
#include <cuda_runtime.h>
#include <cuda_fp16.h>
#include <stdint.h>
#include <math.h>

// Problem constants (fixed by reference setup_inputs)
#define BB 8192
#define DD 1024
#define TEMP 10.0f

// GEMM tiling: CTA 128x256, 4 warps (2x2), warp tile 64x128, BK=32, 3 stages
#define BM 128
#define BN 256
#define BK 32
#define STAGES 3
#define ROWB 80                    // bytes per smem row (32 fp16 = 64B + 16B pad)
#define A_BYTES (BM * ROWB)        // 10240
#define B_BYTES (BN * ROWB)        // 20480
#define STAGE_BYTES (A_BYTES + B_BYTES)   // 30720
#define NTX 32                     // 8192 / BN
#define NTY 64                     // 8192 / BM

// Scratch (allocation-free rule: __device__ globals)
__device__ __half g_imgh[BB * DD];
__device__ __half g_txth[BB * DD];
__device__ float g_partial[NTX * NTY];

// ---------------------------------------------------------------------------
// helpers
// ---------------------------------------------------------------------------
__device__ __forceinline__ uint32_t smem_u32(const void* p) {
    uint32_t a;
    asm("{ .reg .u64 t; cvta.to.shared.u64 t, %1; cvt.u32.u64 %0, t; }" : "=r"(a) : "l"(p));
    return a;
}
__device__ __forceinline__ void cp_async16(uint32_t dst, const void* src) {
    asm volatile("cp.async.cg.shared.global [%0], [%1], 16;" :: "r"(dst), "l"(src));
}
__device__ __forceinline__ void cp_commit() {
    asm volatile("cp.async.commit_group;" ::: "memory");
}
__device__ __forceinline__ void cp_wait1() {
    asm volatile("cp.async.wait_group 1;" ::: "memory");
}
__device__ __forceinline__ void ldsm_x4(uint32_t* r, uint32_t addr) {
    asm volatile("ldmatrix.sync.aligned.m8n8.x4.shared.b16 {%0,%1,%2,%3}, [%4];"
                 : "=r"(r[0]), "=r"(r[1]), "=r"(r[2]), "=r"(r[3]) : "r"(addr));
}
// fp16 in, fp16 accumulate (packed half2 x2)
__device__ __forceinline__ void mma_f16(uint32_t* c, const uint32_t* a, const uint32_t* b) {
    asm volatile(
        "mma.sync.aligned.m16n8k16.row.col.f16.f16.f16.f16 "
        "{%0,%1}, {%2,%3,%4,%5}, {%6,%7}, {%0,%1};"
        : "+r"(c[0]), "+r"(c[1])
        : "r"(a[0]), "r"(a[1]), "r"(a[2]), "r"(a[3]), "r"(b[0]), "r"(b[1]));
}

// ---------------------------------------------------------------------------
// Kernel 1: L2-normalize rows, emit fp16. blocks [0,BB)->image, [BB,2BB)->text
// ---------------------------------------------------------------------------
__global__ __launch_bounds__(256) void normalize_f16_k(const float* __restrict__ text,
                                                       const float* __restrict__ image) {
    int row = blockIdx.x;
    const float* src;
    __half* dst;
    if (row < BB) {
        src = image + (size_t)row * DD;
        dst = g_imgh + (size_t)row * DD;
    } else {
        int r = row - BB;
        src = text + (size_t)r * DD;
        dst = g_txth + (size_t)r * DD;
    }
    int t = threadIdx.x;
    float4 v = ((const float4*)src)[t];
    float ss = v.x * v.x + v.y * v.y + v.z * v.z + v.w * v.w;
    #pragma unroll
    for (int o = 16; o > 0; o >>= 1) ss += __shfl_xor_sync(0xffffffffu, ss, o);

    __shared__ float ws[8];
    int warp = t >> 5, lane = t & 31;
    if (lane == 0) ws[warp] = ss;
    __syncthreads();
    if (warp == 0) {
        float s2 = (lane < 8) ? ws[lane] : 0.f;
        #pragma unroll
        for (int o = 4; o > 0; o >>= 1) s2 += __shfl_xor_sync(0xffffffffu, s2, o);
        if (lane == 0) ws[0] = s2;
    }
    __syncthreads();
    float s = 1.0f / fmaxf(sqrtf(ws[0]), 1e-12f);   // torch F.normalize eps
    __half2 p0 = __floats2half2_rn(v.x * s, v.y * s);
    __half2 p1 = __floats2half2_rn(v.z * s, v.w * s);
    uint2 u;
    u.x = *reinterpret_cast<uint32_t*>(&p0);
    u.y = *reinterpret_cast<uint32_t*>(&p1);
    *reinterpret_cast<uint2*>(dst + t * 4) = u;
}

// ---------------------------------------------------------------------------
// Kernel 2: fp16 mma.sync GEMM, CTA 128x256, 4 warps (2x2), warp tile 64x128,
// fp16 accumulators, 3-stage cp.async, single barrier per K-iter,
// fused sigmoid loss epilogue.
// ---------------------------------------------------------------------------
__global__ __launch_bounds__(128, 2) void gemm_loss_mma(const float* __restrict__ bias) {
    extern __shared__ char smem[];
    const uint32_t sbase = smem_u32(smem);
    const int tid = threadIdx.x;
    const int wid = tid >> 5;
    const int lane = tid & 31;
    const int bx = blockIdx.x;   // N tile (txt rows)
    const int by = blockIdx.y;   // M tile (img rows)

    const int wm = wid >> 1;     // 0..1 (64-row slab)
    const int wn = wid & 1;      // 0..1 (128-col slab)

    // accumulators: 4 m16 x 16 n8 x 2 packed-half2 regs (= 128 regs)
    uint32_t acc[4][16][2];
    #pragma unroll
    for (int i = 0; i < 4; i++)
        #pragma unroll
        for (int j = 0; j < 16; j++) { acc[i][j][0] = 0u; acc[i][j][1] = 0u; }

    const __half* ag = g_imgh + (size_t)(by * BM) * DD;
    const __half* bg = g_txth + (size_t)(bx * BN) * DD;

    // loader: stage = A(128 rows) + B(256 rows) x 64B = 1536 x 16B chunks,
    // 12 per thread
    auto issue_stage = [&](int kc, int stg) {
        uint32_t abase = sbase + stg * STAGE_BYTES;
        #pragma unroll
        for (int o = 0; o < 12; o++) {
            int idx = o * 128 + tid;
            int ch = idx & 3;
            if (idx < 512) {                 // A: 128 rows
                int r = idx >> 2;
                cp_async16(abase + r * ROWB + ch * 16,
                           ag + (size_t)r * DD + kc * BK + ch * 8);
            } else {                         // B: 256 rows
                int r = (idx >> 2) - 128;
                cp_async16(abase + A_BYTES + r * ROWB + ch * 16,
                           bg + (size_t)r * DD + kc * BK + ch * 8);
            }
        }
        cp_commit();
    };

    issue_stage(0, 0);
    issue_stage(1, 1);

    // ldmatrix address components
    const int arow = lane & 15;
    const uint32_t ahi = (lane >> 4) * 16;
    const int bmi = lane >> 3;
    const int brow = lane & 7;
    const int bnoff = (bmi >> 1) * 8;
    const uint32_t bhi = (bmi & 1) * 16;

    const int NKI = DD / BK;   // 32
    for (int kc = 0; kc < NKI; kc++) {
        cp_wait1();
        __syncthreads();   // single barrier: orders prior-iter reads of stage
                           // (kc-1)%3 before its overwrite as (kc+2)%3, and
                           // publishes stage kc%3
        if (kc + 2 < NKI) issue_stage(kc + 2, (kc + 2) % STAGES);
        else cp_commit();   // keep wait_group accounting uniform

        const uint32_t abase = sbase + (kc % STAGES) * STAGE_BYTES;
        const uint32_t bbase = abase + A_BYTES;

        #pragma unroll
        for (int ks = 0; ks < 2; ks++) {
            uint32_t afrag[4][4], bfrag[8][4];
            #pragma unroll
            for (int mt = 0; mt < 4; mt++)
                ldsm_x4(afrag[mt], abase + (wm * 64 + mt * 16 + arow) * ROWB + ks * 32 + ahi);
            #pragma unroll
            for (int p = 0; p < 8; p++)   // n8 pairs (2p, 2p+1) over 128 cols
                ldsm_x4(bfrag[p], bbase + (wn * 128 + p * 16 + bnoff + brow) * ROWB + ks * 32 + bhi);

            #pragma unroll
            for (int mt = 0; mt < 4; mt++)
                #pragma unroll
                for (int nt = 0; nt < 16; nt++)
                    mma_f16(acc[mt][nt], afrag[mt], &bfrag[nt >> 1][(nt & 1) * 2]);
        }
        // no trailing barrier (single-barrier scheme)
    }

    // ---- fused loss epilogue ----
    // f16 acc layout: reg0 = half2{(gr,gc),(gr,gc+1)}, reg1 = same at gr+8
    const float b0v = bias[0];
    const int gr = lane >> 2;
    const int gc = (lane & 3) * 2;
    float local = 0.f;
    #pragma unroll
    for (int mt = 0; mt < 4; mt++) {
        const int m0 = by * BM + wm * 64 + mt * 16 + gr;
        #pragma unroll
        for (int nt = 0; nt < 16; nt++) {
            const int n0 = bx * BN + wn * 128 + nt * 8 + gc;
            #pragma unroll
            for (int k = 0; k < 2; k++) {
                __half2 h = *reinterpret_cast<__half2*>(&acc[mt][nt][k]);
                float2 sv = __half22float2(h);
                int m = m0 + k * 8;
                #pragma unroll
                for (int e = 0; e < 2; e++) {
                    float sim = (e == 0) ? sv.x : sv.y;
                    float logit = fmaf(sim, -TEMP, b0v);
                    float y = (m == n0 + e) ? logit : -logit;
                    local += fmaxf(y, 0.f) + __logf(1.f + __expf(-fabsf(y)));
                }
            }
        }
    }

    // block reduce -> one partial per CTA (deterministic, no atomics)
    #pragma unroll
    for (int o = 16; o > 0; o >>= 1) local += __shfl_xor_sync(0xffffffffu, local, o);
    __shared__ float red[4];
    if (lane == 0) red[wid] = local;
    __syncthreads();
    if (tid == 0) {
        g_partial[by * NTX + bx] = red[0] + red[1] + red[2] + red[3];
    }
}

// ---------------------------------------------------------------------------
// Kernel 3: reduce NTX*NTY partials -> scalar
// ---------------------------------------------------------------------------
__global__ __launch_bounds__(256) void final_reduce_k(float* __restrict__ out) {
    int t = threadIdx.x;
    float s = 0.f;
    for (int i = t; i < NTX * NTY; i += 256) s += g_partial[i];
    #pragma unroll
    for (int o = 16; o > 0; o >>= 1) s += __shfl_xor_sync(0xffffffffu, s, o);
    __shared__ float ws[8];
    if ((t & 31) == 0) ws[t >> 5] = s;
    __syncthreads();
    if (t == 0) {
        float tot = 0.f;
        #pragma unroll
        for (int i = 0; i < 8; i++) tot += ws[i];
        out[0] = tot / (float)BB;
    }
}

// ---------------------------------------------------------------------------
extern "C" void kernel_launch(void* const* d_in, const int* in_sizes, int n_in,
                              void* d_out, int out_size) {
    const float* text  = (const float*)d_in[0];
    const float* image = (const float*)d_in[1];
    const float* bias  = (const float*)d_in[2];

    const int smem_bytes = STAGES * STAGE_BYTES;   // 92160
    cudaFuncSetAttribute(gemm_loss_mma, cudaFuncAttributeMaxDynamicSharedMemorySize, smem_bytes);

    normalize_f16_k<<<2 * BB, 256>>>(text, image);
    gemm_loss_mma<<<dim3(NTX, NTY), 128, smem_bytes>>>(bias);
    final_reduce_k<<<1, 256>>>((float*)d_out);
}

// round 11
// speedup vs baseline: 2.5892x; 1.0657x over previous
#include <cuda_runtime.h>
#include <cuda_fp16.h>
#include <stdint.h>
#include <math.h>

// Problem constants (fixed by reference setup_inputs)
#define BB 8192
#define DD 1024
#define TEMP 10.0f

// GEMM tiling: CTA 128x128, 4 warps (2x2), warp tile 64x64, BK=32, 3 stages
#define BM 128
#define BN 128
#define BK 32
#define STAGES 3
#define ROWB 80                 // bytes per smem row (32 fp16 = 64B + 16B pad)
#define STAGE_BYTES (2 * BM * ROWB)   // A(10240) + B(10240) = 20480
#define NTX 64
#define NTY 64

// Scratch (allocation-free rule: __device__ globals)
__device__ __half g_imgh[BB * DD];
__device__ __half g_txth[BB * DD];
__device__ float g_partial[NTX * NTY];

// ---------------------------------------------------------------------------
// helpers
// ---------------------------------------------------------------------------
__device__ __forceinline__ uint32_t smem_u32(const void* p) {
    uint32_t a;
    asm("{ .reg .u64 t; cvta.to.shared.u64 t, %1; cvt.u32.u64 %0, t; }" : "=r"(a) : "l"(p));
    return a;
}
__device__ __forceinline__ void cp_async16(uint32_t dst, const void* src) {
    asm volatile("cp.async.cg.shared.global [%0], [%1], 16;" :: "r"(dst), "l"(src));
}
__device__ __forceinline__ void cp_commit() {
    asm volatile("cp.async.commit_group;" ::: "memory");
}
__device__ __forceinline__ void cp_wait1() {
    asm volatile("cp.async.wait_group 1;" ::: "memory");
}
__device__ __forceinline__ void ldsm_x4(uint32_t* r, uint32_t addr) {
    asm volatile("ldmatrix.sync.aligned.m8n8.x4.shared.b16 {%0,%1,%2,%3}, [%4];"
                 : "=r"(r[0]), "=r"(r[1]), "=r"(r[2]), "=r"(r[3]) : "r"(addr));
}
// fp16 in, fp16 accumulate (packed half2 x2)
__device__ __forceinline__ void mma_f16(uint32_t* c, const uint32_t* a, const uint32_t* b) {
    asm volatile(
        "mma.sync.aligned.m16n8k16.row.col.f16.f16.f16.f16 "
        "{%0,%1}, {%2,%3,%4,%5}, {%6,%7}, {%0,%1};"
        : "+r"(c[0]), "+r"(c[1])
        : "r"(a[0]), "r"(a[1]), "r"(a[2]), "r"(a[3]), "r"(b[0]), "r"(b[1]));
}

// ---------------------------------------------------------------------------
// Kernel 1: L2-normalize rows, emit fp16. blocks [0,BB)->image, [BB,2BB)->text
// ---------------------------------------------------------------------------
__global__ __launch_bounds__(256) void normalize_f16_k(const float* __restrict__ text,
                                                       const float* __restrict__ image) {
    int row = blockIdx.x;
    const float* src;
    __half* dst;
    if (row < BB) {
        src = image + (size_t)row * DD;
        dst = g_imgh + (size_t)row * DD;
    } else {
        int r = row - BB;
        src = text + (size_t)r * DD;
        dst = g_txth + (size_t)r * DD;
    }
    int t = threadIdx.x;
    float4 v = ((const float4*)src)[t];
    float ss = v.x * v.x + v.y * v.y + v.z * v.z + v.w * v.w;
    #pragma unroll
    for (int o = 16; o > 0; o >>= 1) ss += __shfl_xor_sync(0xffffffffu, ss, o);

    __shared__ float ws[8];
    int warp = t >> 5, lane = t & 31;
    if (lane == 0) ws[warp] = ss;
    __syncthreads();
    if (warp == 0) {
        float s2 = (lane < 8) ? ws[lane] : 0.f;
        #pragma unroll
        for (int o = 4; o > 0; o >>= 1) s2 += __shfl_xor_sync(0xffffffffu, s2, o);
        if (lane == 0) ws[0] = s2;
    }
    __syncthreads();
    float s = 1.0f / fmaxf(sqrtf(ws[0]), 1e-12f);   // torch F.normalize eps
    __half2 p0 = __floats2half2_rn(v.x * s, v.y * s);
    __half2 p1 = __floats2half2_rn(v.z * s, v.w * s);
    uint2 u;
    u.x = *reinterpret_cast<uint32_t*>(&p0);
    u.y = *reinterpret_cast<uint32_t*>(&p1);
    *reinterpret_cast<uint2*>(dst + t * 4) = u;
}

// ---------------------------------------------------------------------------
// Kernel 2: fp16 mma.sync GEMM (128x128 CTA tile, 4 warps, warp tile 64x64,
// fp16 accumulators), 3-stage cp.async, SINGLE barrier per K-iter,
// fused sigmoid loss epilogue. (R6 champion config + barrier removal.)
// ---------------------------------------------------------------------------
__global__ __launch_bounds__(128, 3) void gemm_loss_mma(const float* __restrict__ bias) {
    extern __shared__ char smem[];
    const uint32_t sbase = smem_u32(smem);
    const int tid = threadIdx.x;
    const int wid = tid >> 5;
    const int lane = tid & 31;
    const int bx = blockIdx.x;   // N tile (txt rows)
    const int by = blockIdx.y;   // M tile (img rows)

    const int wm = wid >> 1;     // 0..1 (64-row slab)
    const int wn = wid & 1;      // 0..1 (64-col slab)

    // accumulators: 4 m16 x 8 n8 x 2 packed-half2 regs
    uint32_t acc[4][8][2];
    #pragma unroll
    for (int i = 0; i < 4; i++)
        #pragma unroll
        for (int j = 0; j < 8; j++) { acc[i][j][0] = 0u; acc[i][j][1] = 0u; }

    const __half* ag = g_imgh + (size_t)(by * BM) * DD;
    const __half* bg = g_txth + (size_t)(bx * BN) * DD;

    // loader: 1024 x 16B chunks per stage, 8 per thread
    auto issue_stage = [&](int kc, int stg) {
        uint32_t abase = sbase + stg * STAGE_BYTES;
        #pragma unroll
        for (int o = 0; o < 8; o++) {
            int idx = o * 128 + tid;
            int r = (idx >> 2) & 127;
            int ch = idx & 3;
            if (idx < 512) {
                cp_async16(abase + r * ROWB + ch * 16,
                           ag + (size_t)r * DD + kc * BK + ch * 8);
            } else {
                cp_async16(abase + 10240 + r * ROWB + ch * 16,
                           bg + (size_t)r * DD + kc * BK + ch * 8);
            }
        }
        cp_commit();
    };

    issue_stage(0, 0);
    issue_stage(1, 1);

    // ldmatrix address components
    const int arow = lane & 15;
    const uint32_t ahi = (lane >> 4) * 16;
    const int bmi = lane >> 3;
    const int brow = lane & 7;
    const int bnoff = (bmi >> 1) * 8;
    const uint32_t bhi = (bmi & 1) * 16;

    const int NKI = DD / BK;   // 32
    for (int kc = 0; kc < NKI; kc++) {
        cp_wait1();
        __syncthreads();   // single barrier: orders every warp's reads of stage
                           // (kc-1)%3 (done before arrival) ahead of its
                           // overwrite as stage (kc+2)%3, and publishes stage kc%3
        if (kc + 2 < NKI) issue_stage(kc + 2, (kc + 2) % STAGES);
        else cp_commit();   // keep wait_group accounting uniform

        const uint32_t abase = sbase + (kc % STAGES) * STAGE_BYTES;
        const uint32_t bbase = abase + 10240;

        #pragma unroll
        for (int ks = 0; ks < 2; ks++) {
            uint32_t afrag[4][4], bfrag[4][4];
            #pragma unroll
            for (int mt = 0; mt < 4; mt++)
                ldsm_x4(afrag[mt], abase + (wm * 64 + mt * 16 + arow) * ROWB + ks * 32 + ahi);
            #pragma unroll
            for (int p = 0; p < 4; p++)   // n8 pairs (2p, 2p+1)
                ldsm_x4(bfrag[p], bbase + (wn * 64 + p * 16 + bnoff + brow) * ROWB + ks * 32 + bhi);

            #pragma unroll
            for (int mt = 0; mt < 4; mt++)
                #pragma unroll
                for (int nt = 0; nt < 8; nt++)
                    mma_f16(acc[mt][nt], afrag[mt], &bfrag[nt >> 1][(nt & 1) * 2]);
        }
        // no trailing barrier (single-barrier scheme; safe with STAGES=3)
    }

    // ---- fused loss epilogue ----
    // f16 acc layout: reg0 = half2{(gr,gc),(gr,gc+1)}, reg1 = same at gr+8
    const float b0v = bias[0];
    const int gr = lane >> 2;
    const int gc = (lane & 3) * 2;
    float local = 0.f;
    #pragma unroll
    for (int mt = 0; mt < 4; mt++) {
        const int m0 = by * BM + wm * 64 + mt * 16 + gr;
        #pragma unroll
        for (int nt = 0; nt < 8; nt++) {
            const int n0 = bx * BN + wn * 64 + nt * 8 + gc;
            #pragma unroll
            for (int k = 0; k < 2; k++) {
                __half2 h = *reinterpret_cast<__half2*>(&acc[mt][nt][k]);
                float2 sv = __half22float2(h);
                int m = m0 + k * 8;
                #pragma unroll
                for (int e = 0; e < 2; e++) {
                    float sim = (e == 0) ? sv.x : sv.y;
                    float logit = fmaf(sim, -TEMP, b0v);
                    float y = (m == n0 + e) ? logit : -logit;
                    local += fmaxf(y, 0.f) + __logf(1.f + __expf(-fabsf(y)));
                }
            }
        }
    }

    // block reduce -> one partial per CTA (deterministic, no atomics)
    #pragma unroll
    for (int o = 16; o > 0; o >>= 1) local += __shfl_xor_sync(0xffffffffu, local, o);
    __shared__ float red[4];
    if (lane == 0) red[wid] = local;
    __syncthreads();
    if (tid == 0) {
        g_partial[by * NTX + bx] = red[0] + red[1] + red[2] + red[3];
    }
}

// ---------------------------------------------------------------------------
// Kernel 3: reduce NTX*NTY partials -> scalar
// ---------------------------------------------------------------------------
__global__ __launch_bounds__(256) void final_reduce_k(float* __restrict__ out) {
    int t = threadIdx.x;
    float s = 0.f;
    for (int i = t; i < NTX * NTY; i += 256) s += g_partial[i];
    #pragma unroll
    for (int o = 16; o > 0; o >>= 1) s += __shfl_xor_sync(0xffffffffu, s, o);
    __shared__ float ws[8];
    if ((t & 31) == 0) ws[t >> 5] = s;
    __syncthreads();
    if (t == 0) {
        float tot = 0.f;
        #pragma unroll
        for (int i = 0; i < 8; i++) tot += ws[i];
        out[0] = tot / (float)BB;
    }
}

// ---------------------------------------------------------------------------
extern "C" void kernel_launch(void* const* d_in, const int* in_sizes, int n_in,
                              void* d_out, int out_size) {
    const float* text  = (const float*)d_in[0];
    const float* image = (const float*)d_in[1];
    const float* bias  = (const float*)d_in[2];

    const int smem_bytes = STAGES * STAGE_BYTES;   // 61440
    cudaFuncSetAttribute(gemm_loss_mma, cudaFuncAttributeMaxDynamicSharedMemorySize, smem_bytes);

    normalize_f16_k<<<2 * BB, 256>>>(text, image);
    gemm_loss_mma<<<dim3(NTX, NTY), 128, smem_bytes>>>(bias);
    final_reduce_k<<<1, 256>>>((float*)d_out);
}